// round 1
// baseline (speedup 1.0000x reference)
#include <cuda_runtime.h>
#include <cstdint>
#include <cstdio>

// ---------------------------------------------------------------------------
// DyResConv inference, batch=1:
//   x: (1,768,120,120) f32
//   convs: (3,768,768,3,3) f32
//   routing -> r(3,768); w[o,i,u,v] = sum_e r[e,o]*convs[e,o,i,u,v]
//   y = conv2d(x, w, stride1, pad1)  -> (1,768,120,120) f32
// ---------------------------------------------------------------------------

#define CCH 768
#define SQZ 48
#define HW_ 14400
#define KTOT 6912   // 9 * 768, reordered as k = tap*768 + ic

// scratch (device globals; no allocation allowed)
__device__ float d_att[2304 * 25];
__device__ float d_a3[CCH * 9];
__device__ float d_route[2304];
__device__ float d_w2[CCH * KTOT];   // w2[oc][tap*768+ic], 21.2 MB

// bicubic 3->5 matrix (a=-0.75, align_corners=False, border replicate)
__constant__ float c_M35[5][3] = {
    { 1.096f, -0.096f,  0.000f},
    { 0.612f,  0.460f, -0.072f},
    { 0.000f,  1.000f,  0.000f},
    {-0.072f,  0.460f,  0.612f},
    { 0.000f, -0.096f,  1.096f}
};

// ---------------------------------------------------------------------------
// 1) pooling: per channel compute a1 (global mean), a3 (3x3 block means),
//    a5 (5x5 block means). Writes att rows for a1 and a5, a3 to d_a3.
// ---------------------------------------------------------------------------
__global__ void pool_kernel(const float* __restrict__ x) {
    const int c = blockIdx.x;
    __shared__ float s5[25];
    __shared__ float s3[9];
    const int tid = threadIdx.x;
    if (tid < 25) s5[tid] = 0.f;
    if (tid < 9)  s3[tid] = 0.f;
    __syncthreads();

    const float* xc = x + (size_t)c * HW_;
    // 1800 tasks: (row h, 8-wide col block wb)
    for (int tsk = tid; tsk < 1800; tsk += blockDim.x) {
        int h = tsk / 15;
        int wb = tsk - h * 15;
        int base = h * 120 + wb * 8;
        float s = 0.f;
#pragma unroll
        for (int j = 0; j < 8; j++) s += xc[base + j];
        int w0 = wb * 8;
        atomicAdd(&s5[(h / 24) * 5 + (w0 / 24)], s);
        atomicAdd(&s3[(h / 40) * 3 + (w0 / 40)], s);
    }
    __syncthreads();

    if (tid < 25) d_att[(size_t)(1536 + c) * 25 + tid] = s5[tid] * (1.f / 576.f);
    if (tid < 9)  d_a3[c * 9 + tid] = s3[tid] * (1.f / 1600.f);
    if (tid == 0) {
        float tot = 0.f;
#pragma unroll
        for (int j = 0; j < 25; j++) tot += s5[j];
        float m = tot * (1.f / 14400.f);
#pragma unroll
        for (int pq = 0; pq < 25; pq++) d_att[(size_t)c * 25 + pq] = m;
    }
}

// ---------------------------------------------------------------------------
// 2) bicubic upsample a3 (3x3) -> a3u (5x5), into att rows 768..1535
// ---------------------------------------------------------------------------
__global__ void upsample_kernel() {
    const int c = blockIdx.x;
    __shared__ float a3l[9];
    int tid = threadIdx.x;
    if (tid < 9) a3l[tid] = d_a3[c * 9 + tid];
    __syncthreads();
    if (tid < 25) {
        int p = tid / 5, q = tid - p * 5;
        float s = 0.f;
#pragma unroll
        for (int i = 0; i < 3; i++)
#pragma unroll
            for (int j = 0; j < 3; j++)
                s += c_M35[p][i] * c_M35[q][j] * a3l[i * 3 + j];
        d_att[(size_t)(768 + c) * 25 + tid] = s;
    }
}

// ---------------------------------------------------------------------------
// 3) routing net: pw1 -> relu -> dw1(valid) -> relu -> dw2(valid) -> relu
//    -> pw2 -> sigmoid. Single block.
// ---------------------------------------------------------------------------
__global__ void route_kernel(const float* __restrict__ w_pw1,
                             const float* __restrict__ w_dw1,
                             const float* __restrict__ w_dw2,
                             const float* __restrict__ w_pw2) {
    __shared__ float h1[SQZ * 25];
    __shared__ float h2[SQZ * 9];
    __shared__ float h3[SQZ];
    const int tid = threadIdx.x;

    // stage 1: 48x25 = pw1 * att  (att is 2304 x 25)
    for (int tsk = tid; tsk < SQZ * 25; tsk += blockDim.x) {
        int s = tsk / 25, pq = tsk - s * 25;
        const float* wr = w_pw1 + (size_t)s * 2304;
        float acc = 0.f;
        for (int ch = 0; ch < 2304; ch++)
            acc += wr[ch] * d_att[(size_t)ch * 25 + pq];
        h1[tsk] = fmaxf(acc, 0.f);
    }
    __syncthreads();

    // stage 2: depthwise 3x3 valid: 5x5 -> 3x3
    for (int tsk = tid; tsk < SQZ * 9; tsk += blockDim.x) {
        int s = tsk / 9;
        int r = tsk - s * 9;
        int p = r / 3, q = r - p * 3;
        float acc = 0.f;
#pragma unroll
        for (int u = 0; u < 3; u++)
#pragma unroll
            for (int v = 0; v < 3; v++)
                acc += h1[s * 25 + (p + u) * 5 + (q + v)] * w_dw1[s * 9 + u * 3 + v];
        h2[tsk] = fmaxf(acc, 0.f);
    }
    __syncthreads();

    // stage 3: depthwise 3x3 valid: 3x3 -> 1x1
    if (tid < SQZ) {
        float acc = 0.f;
#pragma unroll
        for (int uv = 0; uv < 9; uv++)
            acc += h2[tid * 9 + uv] * w_dw2[tid * 9 + uv];
        h3[tid] = fmaxf(acc, 0.f);
    }
    __syncthreads();

    // stage 4: pw2 + sigmoid -> 2304 gates
    for (int o = tid; o < 2304; o += blockDim.x) {
        const float* wr = w_pw2 + (size_t)o * SQZ;
        float acc = 0.f;
#pragma unroll
        for (int s = 0; s < SQZ; s++) acc += wr[s] * h3[s];
        d_route[o] = 1.f / (1.f + expf(-acc));
    }
}

// ---------------------------------------------------------------------------
// 4) weight synthesis: w2[oc][tap*768+ic] = sum_e r[e,oc]*convs[e,oc,ic,tap]
//    one block per oc; smem transpose (ic,tap)->(tap,ic), conflict-free.
// ---------------------------------------------------------------------------
__global__ void wsyn_kernel(const float* __restrict__ convs) {
    const int oc = blockIdx.x;
    __shared__ float ws[KTOT];    // 27648 B
    const int tid = threadIdx.x;

    const float r0 = d_route[oc];
    const float r1 = d_route[768 + oc];
    const float r2 = d_route[1536 + oc];
    const float* c0 = convs + (size_t)oc * KTOT;                  // e=0
    const float* c1 = c0 + (size_t)768 * KTOT;                    // e=1
    const float* c2 = c1 + (size_t)768 * KTOT;                    // e=2

#pragma unroll
    for (int j = 0; j < 27; j++) {
        int i = tid + j * 256;     // linear ic*9+tap
        ws[i] = r0 * c0[i] + r1 * c1[i] + r2 * c2[i];
    }
    __syncthreads();

    float* wr = d_w2 + (size_t)oc * KTOT;
#pragma unroll
    for (int j = 0; j < 27; j++) {
        int idx = tid + j * 256;   // idx = tap*768 + ic
        int tap = idx / 768;
        int ic = idx - tap * 768;
        wr[idx] = ws[ic * 9 + tap];   // stride-9 smem read: gcd(9,32)=1 -> no conflicts
    }
}

// ---------------------------------------------------------------------------
// 5) main conv as implicit GEMM with tf32 mma.sync
//    C[768 x 14400] = W2[768 x 6912] * im2col(x)[6912 x 14400]
//    BM=128, BN=256, BK=16 (each K-tile has constant tap), 256 thr, 8 warps
// ---------------------------------------------------------------------------
__device__ __forceinline__ float tf32r(float f) {
    uint32_t u;
    asm("cvt.rna.tf32.f32 %0, %1;" : "=r"(u) : "f"(f));
    return __uint_as_float(u);
}

__device__ __forceinline__ void mma_tf32(float* c, const float* a, const float* b) {
    asm volatile(
        "mma.sync.aligned.m16n8k8.row.col.f32.tf32.tf32.f32 "
        "{%0,%1,%2,%3}, {%4,%5,%6,%7}, {%8,%9}, {%0,%1,%2,%3};\n"
        : "+f"(c[0]), "+f"(c[1]), "+f"(c[2]), "+f"(c[3])
        : "r"(__float_as_uint(a[0])), "r"(__float_as_uint(a[1])),
          "r"(__float_as_uint(a[2])), "r"(__float_as_uint(a[3])),
          "r"(__float_as_uint(b[0])), "r"(__float_as_uint(b[1])));
}

#define SA 132
#define SB 260
#define NKIT 432    // 6912 / 16

__global__ void __launch_bounds__(256, 1)
conv_gemm_kernel(const float* __restrict__ x, float* __restrict__ y) {
    extern __shared__ float sm[];
    float* As = sm;                  // [2][16][SA]
    float* Bs = sm + 2 * 16 * SA;    // [2][16][SB]

    const int tid = threadIdx.x;
    const int lane = tid & 31;
    const int g = lane >> 2, t = lane & 3;
    const int warp = tid >> 5;
    const int wm = warp >> 2, wn = warp & 3;   // 2 x 4 warp grid, 64x64 tiles
    const int oc0 = blockIdx.y * 128;
    const int n0 = blockIdx.x * 256;

    // per-thread pixel for B fill
    const int pix = n0 + tid;
    const int h = pix / 120;
    const int w = pix - h * 120;
    const bool pixok = pix < HW_;

    // A fill task decomposition: 512 float4 slots, 2 per thread
    const int ocl = tid >> 2;    // 0..63
    const int kq = tid & 3;      // which k-quad

    float4 aR[2];
    float bR[16];

    auto ldgA = [&](int it) {
        int k0 = it * 16;
#pragma unroll
        for (int i = 0; i < 2; i++) {
            int oo = ocl + i * 64;
            aR[i] = *reinterpret_cast<const float4*>(
                d_w2 + (size_t)(oc0 + oo) * KTOT + k0 + kq * 4);
        }
    };
    auto stsA = [&](int st) {
        float* dst = As + st * (16 * SA);
#pragma unroll
        for (int i = 0; i < 2; i++) {
            int oo = ocl + i * 64;
            dst[(kq * 4 + 0) * SA + oo] = tf32r(aR[i].x);
            dst[(kq * 4 + 1) * SA + oo] = tf32r(aR[i].y);
            dst[(kq * 4 + 2) * SA + oo] = tf32r(aR[i].z);
            dst[(kq * 4 + 3) * SA + oo] = tf32r(aR[i].w);
        }
    };
    auto ldgB = [&](int it) {
        int tap = it / 48;                    // constant within the K-tile
        int ic0 = (it - tap * 48) * 16;
        int du = tap / 3;
        int dv = tap - du * 3;
        int hh = h + du - 1;
        int ww = w + dv - 1;
        bool valid = pixok && ((unsigned)hh < 120u) && ((unsigned)ww < 120u);
        const float* p = valid ? (x + (size_t)ic0 * HW_ + hh * 120 + ww) : x;
        if (valid) {
#pragma unroll
            for (int k = 0; k < 16; k++) bR[k] = p[(size_t)k * HW_];
        } else {
#pragma unroll
            for (int k = 0; k < 16; k++) bR[k] = 0.f;
        }
    };
    auto stsB = [&](int st) {
        float* dst = Bs + st * (16 * SB);
#pragma unroll
        for (int k = 0; k < 16; k++) dst[k * SB + tid] = tf32r(bR[k]);
    };

    float acc[4][8][4];
#pragma unroll
    for (int i = 0; i < 4; i++)
#pragma unroll
        for (int j = 0; j < 8; j++)
#pragma unroll
            for (int r = 0; r < 4; r++) acc[i][j][r] = 0.f;

    auto compute = [&](int st) {
        const float* A = As + st * (16 * SA);
        const float* B = Bs + st * (16 * SB);
#pragma unroll
        for (int ks = 0; ks < 2; ++ks) {
            const int kb = ks * 8;
            float a[4][4], b[8][2];
#pragma unroll
            for (int i = 0; i < 4; i++) {
                int row = wm * 64 + i * 16 + g;
                a[i][0] = A[(kb + t) * SA + row];
                a[i][1] = A[(kb + t) * SA + row + 8];
                a[i][2] = A[(kb + t + 4) * SA + row];
                a[i][3] = A[(kb + t + 4) * SA + row + 8];
            }
#pragma unroll
            for (int j = 0; j < 8; j++) {
                int col = wn * 64 + j * 8 + g;
                b[j][0] = B[(kb + t) * SB + col];
                b[j][1] = B[(kb + t + 4) * SB + col];
            }
#pragma unroll
            for (int i = 0; i < 4; i++)
#pragma unroll
                for (int j = 0; j < 8; j++)
                    mma_tf32(acc[i][j], a[i], b[j]);
        }
    };

    ldgA(0); ldgB(0);
    stsA(0); stsB(0);
    __syncthreads();

    for (int it = 0; it < NKIT; ++it) {
        int cur = it & 1;
        bool nx = (it + 1) < NKIT;
        if (nx) { ldgA(it + 1); ldgB(it + 1); }
        compute(cur);
        if (nx) { stsA(cur ^ 1); stsB(cur ^ 1); }
        __syncthreads();
    }

    // epilogue: rows of 4 lanes cover one contiguous 32B sector
#pragma unroll
    for (int i = 0; i < 4; i++) {
        int oc = oc0 + wm * 64 + i * 16 + g;
        float* y0 = y + (size_t)oc * HW_;
#pragma unroll
        for (int j = 0; j < 8; j++) {
            int pj = n0 + wn * 64 + j * 8 + 2 * t;
            if (pj < HW_) {
                *reinterpret_cast<float2*>(y0 + pj) =
                    make_float2(acc[i][j][0], acc[i][j][1]);
                *reinterpret_cast<float2*>(y0 + (size_t)8 * HW_ + pj) =
                    make_float2(acc[i][j][2], acc[i][j][3]);
            }
        }
    }
}

// ---------------------------------------------------------------------------
extern "C" void kernel_launch(void* const* d_in, const int* in_sizes, int n_in,
                              void* d_out, int out_size) {
    const float* x     = (const float*)d_in[0];
    const float* convs = (const float*)d_in[1];
    const float* w_pw1 = (const float*)d_in[2];
    const float* w_dw1 = (const float*)d_in[3];
    const float* w_dw2 = (const float*)d_in[4];
    const float* w_pw2 = (const float*)d_in[5];
    float* y = (float*)d_out;

    pool_kernel<<<768, 256>>>(x);
    upsample_kernel<<<768, 32>>>();
    route_kernel<<<1, 1024>>>(w_pw1, w_dw1, w_dw2, w_pw2);
    wsyn_kernel<<<768, 256>>>(convs);

    const int smem_bytes = (2 * 16 * SA + 2 * 16 * SB) * (int)sizeof(float); // 50176
    cudaFuncSetAttribute(conv_gemm_kernel,
                         cudaFuncAttributeMaxDynamicSharedMemorySize, smem_bytes);
    conv_gemm_kernel<<<dim3(57, 6), 256, smem_bytes>>>(x, y);
}

// round 3
// speedup vs baseline: 1.3179x; 1.3179x over previous
#include <cuda_runtime.h>
#include <cstdint>

// ---------------------------------------------------------------------------
// DyResConv inference, batch=1 — Ampere-path tf32 mma.sync implicit GEMM
// (sm_103 base target: tcgen05/TMEM unavailable in this toolchain)
//   GEMM: C[768 x 14400] = W2[768 x 6912] * im2col(x)
//   k = tap*768 + ic  (tap-major: each BK=32 tile has one constant tap)
// ---------------------------------------------------------------------------

#define CCH 768
#define SQZ 48
#define HW_ 14400
#define KTOT 6912
#define NI   216          // 6912 / 32  K-iterations
#define XPW  128          // padded row stride
#define XPR  124          // padded rows
#define XPPL (XPW * XPR)  // padded plane = 15872

// scratch (device globals; no allocation allowed)
__device__ float d_att[2304 * 25];
__device__ float d_a3[CCH * 9];
__device__ float d_route[2304];
__device__ float d_w2[CCH * KTOT];        // tf32-rounded weights [oc][tap*768+ic]
__device__ float d_xp[CCH * XPPL];        // padded + tf32-rounded x

// bicubic 3->5 matrix (a=-0.75, align_corners=False, border replicate)
__constant__ float c_M35[5][3] = {
    { 1.096f, -0.096f,  0.000f},
    { 0.612f,  0.460f, -0.072f},
    { 0.000f,  1.000f,  0.000f},
    {-0.072f,  0.460f,  0.612f},
    { 0.000f, -0.096f,  1.096f}
};

__device__ __forceinline__ float tf32r(float f) {
    uint32_t u;
    asm("cvt.rna.tf32.f32 %0, %1;" : "=r"(u) : "f"(f));
    return __uint_as_float(u);
}

// ---------------------------------------------------------------------------
// 1) pooling
// ---------------------------------------------------------------------------
__global__ void pool_kernel(const float* __restrict__ x) {
    const int c = blockIdx.x;
    __shared__ float s5[25];
    __shared__ float s3[9];
    const int tid = threadIdx.x;
    if (tid < 25) s5[tid] = 0.f;
    if (tid < 9)  s3[tid] = 0.f;
    __syncthreads();

    const float* xc = x + (size_t)c * HW_;
    for (int tsk = tid; tsk < 1800; tsk += blockDim.x) {
        int h = tsk / 15;
        int wb = tsk - h * 15;
        int base = h * 120 + wb * 8;
        float s = 0.f;
#pragma unroll
        for (int j = 0; j < 8; j++) s += xc[base + j];
        int w0 = wb * 8;
        atomicAdd(&s5[(h / 24) * 5 + (w0 / 24)], s);
        atomicAdd(&s3[(h / 40) * 3 + (w0 / 40)], s);
    }
    __syncthreads();

    if (tid < 25) d_att[(size_t)(1536 + c) * 25 + tid] = s5[tid] * (1.f / 576.f);
    if (tid < 9)  d_a3[c * 9 + tid] = s3[tid] * (1.f / 1600.f);
    if (tid == 0) {
        float tot = 0.f;
#pragma unroll
        for (int j = 0; j < 25; j++) tot += s5[j];
        float m = tot * (1.f / 14400.f);
#pragma unroll
        for (int pq = 0; pq < 25; pq++) d_att[(size_t)c * 25 + pq] = m;
    }
}

// ---------------------------------------------------------------------------
// 2) routing net (upsample fused)
// ---------------------------------------------------------------------------
__global__ void route_kernel(const float* __restrict__ w_pw1,
                             const float* __restrict__ w_dw1,
                             const float* __restrict__ w_dw2,
                             const float* __restrict__ w_pw2) {
    __shared__ float h1[SQZ * 25];
    __shared__ float h2[SQZ * 9];
    __shared__ float h3[SQZ];
    const int tid = threadIdx.x;

    for (int tsk = tid; tsk < 768 * 25; tsk += blockDim.x) {
        int c = tsk / 25, pq = tsk - c * 25;
        int p = pq / 5, q = pq - p * 5;
        float s = 0.f;
#pragma unroll
        for (int i = 0; i < 3; i++)
#pragma unroll
            for (int j = 0; j < 3; j++)
                s += c_M35[p][i] * c_M35[q][j] * d_a3[c * 9 + i * 3 + j];
        d_att[(size_t)(768 + c) * 25 + pq] = s;
    }
    __syncthreads();

    for (int tsk = tid; tsk < SQZ * 25; tsk += blockDim.x) {
        int s = tsk / 25, pq = tsk - s * 25;
        const float* wr = w_pw1 + (size_t)s * 2304;
        float acc = 0.f;
        for (int ch = 0; ch < 2304; ch++)
            acc += wr[ch] * d_att[(size_t)ch * 25 + pq];
        h1[tsk] = fmaxf(acc, 0.f);
    }
    __syncthreads();

    for (int tsk = tid; tsk < SQZ * 9; tsk += blockDim.x) {
        int s = tsk / 9;
        int r = tsk - s * 9;
        int p = r / 3, q = r - p * 3;
        float acc = 0.f;
#pragma unroll
        for (int u = 0; u < 3; u++)
#pragma unroll
            for (int v = 0; v < 3; v++)
                acc += h1[s * 25 + (p + u) * 5 + (q + v)] * w_dw1[s * 9 + u * 3 + v];
        h2[tsk] = fmaxf(acc, 0.f);
    }
    __syncthreads();

    if (tid < SQZ) {
        float acc = 0.f;
#pragma unroll
        for (int uv = 0; uv < 9; uv++)
            acc += h2[tid * 9 + uv] * w_dw2[tid * 9 + uv];
        h3[tid] = fmaxf(acc, 0.f);
    }
    __syncthreads();

    for (int o = tid; o < 2304; o += blockDim.x) {
        const float* wr = w_pw2 + (size_t)o * SQZ;
        float acc = 0.f;
#pragma unroll
        for (int s = 0; s < SQZ; s++) acc += wr[s] * h3[s];
        d_route[o] = 1.f / (1.f + expf(-acc));
    }
}

// ---------------------------------------------------------------------------
// 3) weight synthesis (tf32-rounded output)
// ---------------------------------------------------------------------------
__global__ void wsyn_kernel(const float* __restrict__ convs) {
    const int oc = blockIdx.x;
    __shared__ float ws[KTOT];
    const int tid = threadIdx.x;

    const float r0 = d_route[oc];
    const float r1 = d_route[768 + oc];
    const float r2 = d_route[1536 + oc];
    const float* c0 = convs + (size_t)oc * KTOT;
    const float* c1 = c0 + (size_t)768 * KTOT;
    const float* c2 = c1 + (size_t)768 * KTOT;

#pragma unroll
    for (int j = 0; j < 27; j++) {
        int i = tid + j * 256;
        ws[i] = r0 * c0[i] + r1 * c1[i] + r2 * c2[i];
    }
    __syncthreads();

    float* wr = d_w2 + (size_t)oc * KTOT;
#pragma unroll
    for (int j = 0; j < 27; j++) {
        int idx = tid + j * 256;       // idx = tap*768 + ic
        int tap = idx / 768;
        int ic = idx - tap * 768;
        wr[idx] = tf32r(ws[ic * 9 + tap]);
    }
}

// ---------------------------------------------------------------------------
// 4) pad + round x:  d_xp[ic][h+1][w+1] = tf32(x[ic][h][w]), borders = 0
// ---------------------------------------------------------------------------
__global__ void pad_kernel(const float* __restrict__ x) {
    const int ic = blockIdx.x;
    const int tid = threadIdx.x;
    float* dst = d_xp + (size_t)ic * XPPL;
    for (int i = tid; i < XPPL; i += blockDim.x) {
        int r = i >> 7, cix = i & 127;
        bool interior = (r >= 1 && r <= 120 && cix >= 1 && cix <= 120);
        if (!interior) dst[i] = 0.f;
    }
    __syncthreads();
    const float* src = x + (size_t)ic * HW_;
    for (int p = tid; p < HW_; p += blockDim.x) {
        int h = p / 120, w = p - h * 120;
        dst[(h + 1) * XPW + (w + 1)] = tf32r(src[p]);
    }
}

// ---------------------------------------------------------------------------
// 5) conv GEMM: BM=128, BN=256, BK=32, 256 thr (8 warps, 64x64 warp tiles)
//    A: cp.async 3-stage, layout [m][36] floats (conflict-free scalar LDS)
//    B: LDG(prefetch)+STS, layout [ks*4+t][260][2] k-pairs (LDS.64 frags)
// ---------------------------------------------------------------------------
__device__ __forceinline__ void mma_tf32(float* c, const float* a, const float* b) {
    asm volatile(
        "mma.sync.aligned.m16n8k8.row.col.f32.tf32.tf32.f32 "
        "{%0,%1,%2,%3}, {%4,%5,%6,%7}, {%8,%9}, {%0,%1,%2,%3};\n"
        : "+f"(c[0]), "+f"(c[1]), "+f"(c[2]), "+f"(c[3])
        : "r"(__float_as_uint(a[0])), "r"(__float_as_uint(a[1])),
          "r"(__float_as_uint(a[2])), "r"(__float_as_uint(a[3])),
          "r"(__float_as_uint(b[0])), "r"(__float_as_uint(b[1])));
}

__device__ __forceinline__ uint32_t cvta_smem(const void* p) {
    uint32_t a;
    asm("{ .reg .u64 t; cvta.to.shared.u64 t, %1; cvt.u32.u64 %0, t; }"
        : "=r"(a) : "l"(p));
    return a;
}

__device__ __forceinline__ void cp16(uint32_t dst, const void* src) {
    asm volatile("cp.async.cg.shared.global [%0], [%1], 16;\n"
                 :: "r"(dst), "l"(src) : "memory");
}

#define ASTRIDE 36                  // floats per A row in smem
#define A_STG_F (128 * ASTRIDE)     // 4608 floats / stage
#define B_STG_F (16 * 260 * 2)      // 8320 floats / stage
#define SMEM_REQ ((3 * A_STG_F + 2 * B_STG_F) * 4)   // 121856 B

__global__ void __launch_bounds__(256, 1)
conv_gemm_kernel(float* __restrict__ y) {
    extern __shared__ float sm[];
    float* As = sm;                      // 3 stages
    float* Bs = sm + 3 * A_STG_F;        // 2 stages
    const uint32_t As_u32 = cvta_smem(As);

    const int tid = threadIdx.x;
    const int lane = tid & 31;
    const int g = lane >> 2, t = lane & 3;
    const int warp = tid >> 5;
    const int wm = warp >> 2, wn = warp & 3;   // 2x4 warps, 64x64 tiles
    const int oc0 = blockIdx.y * 128;
    const int n0 = blockIdx.x * 256;

    // B gather coords (padded buffer: never out of bounds, borders zero)
    const int pix = n0 + tid;
    const int phh = pix / 120;
    const int pww = pix - phh * 120;

    const float* aSrc = d_w2 + (size_t)oc0 * KTOT;
    const int arow = tid >> 3;           // c = tid + j*256 -> row = c/8
    const int acb = tid & 7;

    float bR[32];

    auto cpA = [&](int it, int st) {
        uint32_t dbase = As_u32 + (uint32_t)st * (A_STG_F * 4);
        const float* s0 = aSrc + it * 32;
#pragma unroll
        for (int j = 0; j < 4; j++) {
            int row = arow + j * 32;
            cp16(dbase + row * (ASTRIDE * 4) + acb * 16,
                 s0 + (size_t)row * KTOT + acb * 4);
        }
        asm volatile("cp.async.commit_group;\n" ::: "memory");
    };

    auto ldgB = [&](int it) {
        int tap = it / 24;
        int ic0 = (it - tap * 24) * 32;
        int du = tap / 3, dv = tap - du * 3;
        const float* bp = d_xp + (size_t)ic0 * XPPL + (phh + du) * XPW + (pww + dv);
#pragma unroll
        for (int k = 0; k < 32; k++) bR[k] = bp[(size_t)k * XPPL];
    };

    auto stsB = [&](int st) {
        float2* bd = (float2*)(Bs + st * B_STG_F);
#pragma unroll
        for (int ks = 0; ks < 4; ks++)
#pragma unroll
            for (int tt = 0; tt < 4; tt++)
                bd[(ks * 4 + tt) * 260 + tid] =
                    make_float2(bR[ks * 8 + tt], bR[ks * 8 + tt + 4]);
    };

    float acc[4][8][4];
#pragma unroll
    for (int i = 0; i < 4; i++)
#pragma unroll
        for (int j = 0; j < 8; j++)
#pragma unroll
            for (int r = 0; r < 4; r++) acc[i][j][r] = 0.f;

    auto compute = [&](int stA, int stB) {
        const float* A = As + stA * A_STG_F;
        const float2* B = (const float2*)(Bs + stB * B_STG_F);
#pragma unroll
        for (int ks = 0; ks < 4; ++ks) {
            const int kb = ks * 8;
            float a[4][4];
            float2 b[8];
#pragma unroll
            for (int i = 0; i < 4; i++) {
                int row = wm * 64 + i * 16 + g;
                a[i][0] = A[row * ASTRIDE + kb + t];
                a[i][1] = A[(row + 8) * ASTRIDE + kb + t];
                a[i][2] = A[row * ASTRIDE + kb + t + 4];
                a[i][3] = A[(row + 8) * ASTRIDE + kb + t + 4];
            }
#pragma unroll
            for (int j = 0; j < 8; j++) {
                int col = wn * 64 + j * 8 + g;
                b[j] = B[(ks * 4 + t) * 260 + col];
            }
#pragma unroll
            for (int i = 0; i < 4; i++)
#pragma unroll
                for (int j = 0; j < 8; j++)
                    mma_tf32(acc[i][j], a[i], (const float*)&b[j]);
        }
    };

    // prologue
    cpA(0, 0);
    cpA(1, 1);
    ldgB(0);
    stsB(0);
    asm volatile("cp.async.wait_group 1;\n" ::: "memory");   // A0 landed
    __syncthreads();

    for (int it = 0; it < NI; ++it) {
        const int stA = it % 3;
        const int stB = it & 1;
        const bool more2 = (it + 2) < NI;
        const bool more1 = (it + 1) < NI;
        if (more2) cpA(it + 2, (it + 2) % 3);
        if (more1) ldgB(it + 1);
        compute(stA, stB);
        if (more1) {
            stsB(stB ^ 1);
            if (more2) { asm volatile("cp.async.wait_group 1;\n" ::: "memory"); }
            else       { asm volatile("cp.async.wait_group 0;\n" ::: "memory"); }
            __syncthreads();
        }
    }

    // epilogue
#pragma unroll
    for (int i = 0; i < 4; i++) {
        int oc = oc0 + wm * 64 + i * 16 + g;
        float* y0 = y + (size_t)oc * HW_;
#pragma unroll
        for (int j = 0; j < 8; j++) {
            int pj = n0 + wn * 64 + j * 8 + 2 * t;
            if (pj < HW_) {
                *reinterpret_cast<float2*>(y0 + pj) =
                    make_float2(acc[i][j][0], acc[i][j][1]);
                *reinterpret_cast<float2*>(y0 + (size_t)8 * HW_ + pj) =
                    make_float2(acc[i][j][2], acc[i][j][3]);
            }
        }
    }
}

// ---------------------------------------------------------------------------
extern "C" void kernel_launch(void* const* d_in, const int* in_sizes, int n_in,
                              void* d_out, int out_size) {
    const float* x     = (const float*)d_in[0];
    const float* convs = (const float*)d_in[1];
    const float* w_pw1 = (const float*)d_in[2];
    const float* w_dw1 = (const float*)d_in[3];
    const float* w_dw2 = (const float*)d_in[4];
    const float* w_pw2 = (const float*)d_in[5];
    float* y = (float*)d_out;

    pool_kernel<<<768, 256>>>(x);
    route_kernel<<<1, 1024>>>(w_pw1, w_dw1, w_dw2, w_pw2);
    wsyn_kernel<<<768, 256>>>(convs);
    pad_kernel<<<768, 256>>>(x);

    cudaFuncSetAttribute(conv_gemm_kernel,
                         cudaFuncAttributeMaxDynamicSharedMemorySize, SMEM_REQ);
    conv_gemm_kernel<<<dim3(57, 6), 256, SMEM_REQ>>>(y);
}

// round 4
// speedup vs baseline: 1.8771x; 1.4243x over previous
#include <cuda_runtime.h>
#include <cuda_fp16.h>
#include <cstdint>

// ---------------------------------------------------------------------------
// DyResConv inference, batch=1 — fp16 mma.sync m16n8k16 implicit GEMM
// (fp16 mantissa = 11 bits = tf32 precision; 2x MACs per legacy HMMA instr)
//   GEMM: C[768 x 14400] = W2[768 x 6912] * im2col(x)
//   k = tap*768 + ic  (tap-major: each BK=32 tile has one constant tap)
// ---------------------------------------------------------------------------

#define CCH 768
#define SQZ 48
#define HW_ 14400
#define KTOT 6912
#define NI   216          // 6912 / 32  K-iterations
#define XPW  128          // padded row stride
#define XPR  124          // padded rows
#define XPPL (XPW * XPR)  // padded plane = 15872

// scratch (device globals; no allocation allowed)
__device__ float d_att[2304 * 25];
__device__ float d_a3[CCH * 9];
__device__ float d_route[2304];
__device__ __half  d_w2h[CCH * KTOT];           // fp16 weights [oc][tap*768+ic]
__device__ __half2 d_xp2[(CCH / 2) * XPPL];     // padded x, ic-pairs packed

// bicubic 3->5 matrix (a=-0.75, align_corners=False, border replicate)
__constant__ float c_M35[5][3] = {
    { 1.096f, -0.096f,  0.000f},
    { 0.612f,  0.460f, -0.072f},
    { 0.000f,  1.000f,  0.000f},
    {-0.072f,  0.460f,  0.612f},
    { 0.000f, -0.096f,  1.096f}
};

// ---------------------------------------------------------------------------
// 1) pooling
// ---------------------------------------------------------------------------
__global__ void pool_kernel(const float* __restrict__ x) {
    const int c = blockIdx.x;
    __shared__ float s5[25];
    __shared__ float s3[9];
    const int tid = threadIdx.x;
    if (tid < 25) s5[tid] = 0.f;
    if (tid < 9)  s3[tid] = 0.f;
    __syncthreads();

    const float* xc = x + (size_t)c * HW_;
    for (int tsk = tid; tsk < 1800; tsk += blockDim.x) {
        int h = tsk / 15;
        int wb = tsk - h * 15;
        int base = h * 120 + wb * 8;
        float s = 0.f;
#pragma unroll
        for (int j = 0; j < 8; j++) s += xc[base + j];
        int w0 = wb * 8;
        atomicAdd(&s5[(h / 24) * 5 + (w0 / 24)], s);
        atomicAdd(&s3[(h / 40) * 3 + (w0 / 40)], s);
    }
    __syncthreads();

    if (tid < 25) d_att[(size_t)(1536 + c) * 25 + tid] = s5[tid] * (1.f / 576.f);
    if (tid < 9)  d_a3[c * 9 + tid] = s3[tid] * (1.f / 1600.f);
    if (tid == 0) {
        float tot = 0.f;
#pragma unroll
        for (int j = 0; j < 25; j++) tot += s5[j];
        float m = tot * (1.f / 14400.f);
#pragma unroll
        for (int pq = 0; pq < 25; pq++) d_att[(size_t)c * 25 + pq] = m;
    }
}

// ---------------------------------------------------------------------------
// 2) routing net (upsample fused)
// ---------------------------------------------------------------------------
__global__ void route_kernel(const float* __restrict__ w_pw1,
                             const float* __restrict__ w_dw1,
                             const float* __restrict__ w_dw2,
                             const float* __restrict__ w_pw2) {
    __shared__ float h1[SQZ * 25];
    __shared__ float h2[SQZ * 9];
    __shared__ float h3[SQZ];
    const int tid = threadIdx.x;

    for (int tsk = tid; tsk < 768 * 25; tsk += blockDim.x) {
        int c = tsk / 25, pq = tsk - c * 25;
        int p = pq / 5, q = pq - p * 5;
        float s = 0.f;
#pragma unroll
        for (int i = 0; i < 3; i++)
#pragma unroll
            for (int j = 0; j < 3; j++)
                s += c_M35[p][i] * c_M35[q][j] * d_a3[c * 9 + i * 3 + j];
        d_att[(size_t)(768 + c) * 25 + pq] = s;
    }
    __syncthreads();

    for (int tsk = tid; tsk < SQZ * 25; tsk += blockDim.x) {
        int s = tsk / 25, pq = tsk - s * 25;
        const float* wr = w_pw1 + (size_t)s * 2304;
        float acc = 0.f;
        for (int ch = 0; ch < 2304; ch++)
            acc += wr[ch] * d_att[(size_t)ch * 25 + pq];
        h1[tsk] = fmaxf(acc, 0.f);
    }
    __syncthreads();

    for (int tsk = tid; tsk < SQZ * 9; tsk += blockDim.x) {
        int s = tsk / 9;
        int r = tsk - s * 9;
        int p = r / 3, q = r - p * 3;
        float acc = 0.f;
#pragma unroll
        for (int u = 0; u < 3; u++)
#pragma unroll
            for (int v = 0; v < 3; v++)
                acc += h1[s * 25 + (p + u) * 5 + (q + v)] * w_dw1[s * 9 + u * 3 + v];
        h2[tsk] = fmaxf(acc, 0.f);
    }
    __syncthreads();

    if (tid < SQZ) {
        float acc = 0.f;
#pragma unroll
        for (int uv = 0; uv < 9; uv++)
            acc += h2[tid * 9 + uv] * w_dw2[tid * 9 + uv];
        h3[tid] = fmaxf(acc, 0.f);
    }
    __syncthreads();

    for (int o = tid; o < 2304; o += blockDim.x) {
        const float* wr = w_pw2 + (size_t)o * SQZ;
        float acc = 0.f;
#pragma unroll
        for (int s = 0; s < SQZ; s++) acc += wr[s] * h3[s];
        d_route[o] = 1.f / (1.f + expf(-acc));
    }
}

// ---------------------------------------------------------------------------
// 3) weight synthesis -> fp16, tap-major layout
// ---------------------------------------------------------------------------
__global__ void wsyn_kernel(const float* __restrict__ convs) {
    const int oc = blockIdx.x;
    __shared__ float ws[KTOT];
    const int tid = threadIdx.x;

    const float r0 = d_route[oc];
    const float r1 = d_route[768 + oc];
    const float r2 = d_route[1536 + oc];
    const float* c0 = convs + (size_t)oc * KTOT;
    const float* c1 = c0 + (size_t)768 * KTOT;
    const float* c2 = c1 + (size_t)768 * KTOT;

#pragma unroll
    for (int j = 0; j < 27; j++) {
        int i = tid + j * 256;
        ws[i] = r0 * c0[i] + r1 * c1[i] + r2 * c2[i];
    }
    __syncthreads();

    __half* wr = d_w2h + (size_t)oc * KTOT;
#pragma unroll
    for (int j = 0; j < 27; j++) {
        int idx = tid + j * 256;       // idx = tap*768 + ic
        int tap = idx / 768;
        int ic = idx - tap * 768;
        wr[idx] = __float2half(ws[ic * 9 + tap]);
    }
}

// ---------------------------------------------------------------------------
// 4) pad + pack x into ic-pair half2 planes (borders zero)
//    d_xp2[icp][(h+1)*128 + (w+1)] = (half(x[2icp][h][w]), half(x[2icp+1][h][w]))
// ---------------------------------------------------------------------------
__global__ void pad_kernel(const float* __restrict__ x) {
    const int icp = blockIdx.x;           // 0..383
    const int tid = threadIdx.x;
    __half2* dst = d_xp2 + (size_t)icp * XPPL;
    for (int i = tid; i < XPPL; i += blockDim.x) {
        int r = i >> 7, cix = i & 127;
        bool interior = (r >= 1 && r <= 120 && cix >= 1 && cix <= 120);
        if (!interior) dst[i] = __half2half2(__float2half(0.f));
    }
    const float* s0 = x + (size_t)(2 * icp) * HW_;
    const float* s1 = s0 + HW_;
    for (int p = tid; p < HW_; p += blockDim.x) {
        int h = p / 120, w = p - h * 120;
        dst[(h + 1) * XPW + (w + 1)] =
            __floats2half2_rn(s0[p], s1[p]);
    }
}

// ---------------------------------------------------------------------------
// 5) conv GEMM fp16: BM=128, BN=256, BK=32, 256 thr, 2x4 warps (64x64 tiles)
//    A smem: [m][20 half2] rows (k-pairs), stride-20 -> conflict-free LDS.32
//    B smem: [kpair][264] half2 -> conflict-free LDS.32 fragments
// ---------------------------------------------------------------------------
__device__ __forceinline__ void mma_fp16(float* c, const uint32_t* a, const uint32_t* b) {
    asm volatile(
        "mma.sync.aligned.m16n8k16.row.col.f32.f16.f16.f32 "
        "{%0,%1,%2,%3}, {%4,%5,%6,%7}, {%8,%9}, {%0,%1,%2,%3};\n"
        : "+f"(c[0]), "+f"(c[1]), "+f"(c[2]), "+f"(c[3])
        : "r"(a[0]), "r"(a[1]), "r"(a[2]), "r"(a[3]),
          "r"(b[0]), "r"(b[1]));
}

__device__ __forceinline__ uint32_t cvta_smem(const void* p) {
    uint32_t a;
    asm("{ .reg .u64 t; cvta.to.shared.u64 t, %1; cvt.u32.u64 %0, t; }"
        : "=r"(a) : "l"(p));
    return a;
}

__device__ __forceinline__ void cp16(uint32_t dst, const void* src) {
    asm volatile("cp.async.cg.shared.global [%0], [%1], 16;\n"
                 :: "r"(dst), "l"(src) : "memory");
}

#define AS2 20                      // half2 per A row (16 used + 4 pad)
#define A_STG_W (128 * AS2)         // half2 words per A stage = 2560
#define BS2 264                     // half2 per B k-pair row (256 + 8 pad)
#define B_STG_W (16 * BS2)          // half2 words per B stage = 4224
#define SMEM_REQ ((3 * A_STG_W + 2 * B_STG_W) * 4)   // 64512 B

__global__ void __launch_bounds__(256, 1)
conv_gemm_kernel(float* __restrict__ y) {
    extern __shared__ __half2 sm2[];
    __half2* As = sm2;                    // 3 stages
    __half2* Bs = sm2 + 3 * A_STG_W;      // 2 stages
    const uint32_t As_u32 = cvta_smem(As);

    const int tid = threadIdx.x;
    const int lane = tid & 31;
    const int g = lane >> 2, t = lane & 3;
    const int warp = tid >> 5;
    const int wm = warp >> 2, wn = warp & 3;   // 2x4 warps, 64x64 tiles
    const int oc0 = blockIdx.y * 128;
    const int n0 = blockIdx.x * 256;

    // B gather coords (padded buffer: never OOB, borders zero)
    const int pix = n0 + tid;
    const int phh = pix / 120;
    const int pww = pix - phh * 120;

    // A fill: 512 16B-chunks per stage (128 rows x 4), 2 per thread
    const __half* aSrc = d_w2h + (size_t)oc0 * KTOT;
    const int arow = tid >> 1;            // rows 0..127, two threads per row
    const int acb0 = (tid & 1) * 2;       // chunks {0,1} or {2,3}

    __half2 bR[16];

    auto cpA = [&](int it, int st) {
        uint32_t dbase = As_u32 + (uint32_t)st * (A_STG_W * 4);
        const __half* s0 = aSrc + (size_t)arow * KTOT + it * 32;
#pragma unroll
        for (int j = 0; j < 2; j++) {
            int cb = acb0 + j;
            cp16(dbase + arow * (AS2 * 4) + cb * 16, s0 + cb * 8);
        }
        asm volatile("cp.async.commit_group;\n" ::: "memory");
    };

    auto ldgB = [&](int it) {
        int tap = it / 24;
        int icp0 = (it - tap * 24) * 16;
        int du = tap / 3, dv = tap - du * 3;
        const __half2* bp = d_xp2 + (size_t)icp0 * XPPL + (phh + du) * XPW + (pww + dv);
#pragma unroll
        for (int kp = 0; kp < 16; kp++) bR[kp] = bp[(size_t)kp * XPPL];
    };

    auto stsB = [&](int st) {
        __half2* bd = Bs + st * B_STG_W + tid;
#pragma unroll
        for (int kp = 0; kp < 16; kp++) bd[kp * BS2] = bR[kp];
    };

    float acc[4][8][4];
#pragma unroll
    for (int i = 0; i < 4; i++)
#pragma unroll
        for (int j = 0; j < 8; j++)
#pragma unroll
            for (int r = 0; r < 4; r++) acc[i][j][r] = 0.f;

    auto compute = [&](int stA, int stB) {
        const __half2* A = As + stA * A_STG_W;
        const __half2* B = Bs + stB * B_STG_W;
#pragma unroll
        for (int ks = 0; ks < 2; ++ks) {
            const int kb2 = ks * 8;      // k-pair base within BK=32 (0 or 8)
            uint32_t a[4][4], b[8][2];
#pragma unroll
            for (int i = 0; i < 4; i++) {
                int row = wm * 64 + i * 16 + g;
                a[i][0] = *(const uint32_t*)&A[row * AS2 + kb2 + t];
                a[i][1] = *(const uint32_t*)&A[(row + 8) * AS2 + kb2 + t];
                a[i][2] = *(const uint32_t*)&A[row * AS2 + kb2 + t + 4];
                a[i][3] = *(const uint32_t*)&A[(row + 8) * AS2 + kb2 + t + 4];
            }
#pragma unroll
            for (int j = 0; j < 8; j++) {
                int col = wn * 64 + j * 8 + g;
                b[j][0] = *(const uint32_t*)&B[(kb2 + t) * BS2 + col];
                b[j][1] = *(const uint32_t*)&B[(kb2 + t + 4) * BS2 + col];
            }
#pragma unroll
            for (int i = 0; i < 4; i++)
#pragma unroll
                for (int j = 0; j < 8; j++)
                    mma_fp16(acc[i][j], a[i], b[j]);
        }
    };

    // prologue
    cpA(0, 0);
    cpA(1, 1);
    ldgB(0);
    stsB(0);
    asm volatile("cp.async.wait_group 1;\n" ::: "memory");   // A0 landed
    __syncthreads();

    for (int it = 0; it < NI; ++it) {
        const int stA = it % 3;
        const int stB = it & 1;
        const bool more2 = (it + 2) < NI;
        const bool more1 = (it + 1) < NI;
        if (more2) cpA(it + 2, (it + 2) % 3);
        if (more1) ldgB(it + 1);
        compute(stA, stB);
        if (more1) {
            stsB(stB ^ 1);
            if (more2) { asm volatile("cp.async.wait_group 1;\n" ::: "memory"); }
            else       { asm volatile("cp.async.wait_group 0;\n" ::: "memory"); }
            __syncthreads();
        }
    }

    // epilogue
#pragma unroll
    for (int i = 0; i < 4; i++) {
        int oc = oc0 + wm * 64 + i * 16 + g;
        float* y0 = y + (size_t)oc * HW_;
#pragma unroll
        for (int j = 0; j < 8; j++) {
            int pj = n0 + wn * 64 + j * 8 + 2 * t;
            if (pj < HW_) {
                *reinterpret_cast<float2*>(y0 + pj) =
                    make_float2(acc[i][j][0], acc[i][j][1]);
                *reinterpret_cast<float2*>(y0 + (size_t)8 * HW_ + pj) =
                    make_float2(acc[i][j][2], acc[i][j][3]);
            }
        }
    }
}

// tiny tail kernel so conv is the second-to-last launch (ncu capture slot)
__global__ void tail_kernel() {
    d_a3[0] = d_route[0];   // overwritten by pool/route before next use
}

// ---------------------------------------------------------------------------
extern "C" void kernel_launch(void* const* d_in, const int* in_sizes, int n_in,
                              void* d_out, int out_size) {
    const float* x     = (const float*)d_in[0];
    const float* convs = (const float*)d_in[1];
    const float* w_pw1 = (const float*)d_in[2];
    const float* w_dw1 = (const float*)d_in[3];
    const float* w_dw2 = (const float*)d_in[4];
    const float* w_pw2 = (const float*)d_in[5];
    float* y = (float*)d_out;

    pool_kernel<<<768, 256>>>(x);
    route_kernel<<<1, 1024>>>(w_pw1, w_dw1, w_dw2, w_pw2);
    wsyn_kernel<<<768, 256>>>(convs);
    pad_kernel<<<384, 256>>>(x);

    cudaFuncSetAttribute(conv_gemm_kernel,
                         cudaFuncAttributeMaxDynamicSharedMemorySize, SMEM_REQ);
    conv_gemm_kernel<<<dim3(57, 6), 256, SMEM_REQ>>>(y);
    tail_kernel<<<1, 1>>>();
}

// round 5
// speedup vs baseline: 2.0330x; 1.0831x over previous
#include <cuda_runtime.h>
#include <cuda_fp16.h>
#include <cstdint>

// ---------------------------------------------------------------------------
// DyResConv inference, batch=1 — fp16 mma.sync m16n8k16 implicit GEMM
//   GEMM: C[768 x 14400] = W2[768 x 6912] * im2col(x)
//   k = tap*768 + ic  (tap-major: each BK=32 tile has one constant tap)
// R5: pool+pad fused (conv = 4th launch -> ncu capture), BN=128 + occupancy 2
// ---------------------------------------------------------------------------

#define CCH 768
#define SQZ 48
#define HW_ 14400
#define KTOT 6912
#define NI   216          // 6912 / 32  K-iterations
#define XPW  128          // padded row stride
#define XPR  124          // padded rows
#define XPPL (XPW * XPR)  // padded plane = 15872

// scratch (device globals; no allocation allowed)
__device__ float d_att[2304 * 25];
__device__ float d_a3[CCH * 9];
__device__ float d_route[2304];
__device__ __half  d_w2h[CCH * KTOT];           // fp16 weights [oc][tap*768+ic]
__device__ __half2 d_xp2[(CCH / 2) * XPPL];     // padded x, ic-pairs packed

// bicubic 3->5 matrix (a=-0.75, align_corners=False, border replicate)
__constant__ float c_M35[5][3] = {
    { 1.096f, -0.096f,  0.000f},
    { 0.612f,  0.460f, -0.072f},
    { 0.000f,  1.000f,  0.000f},
    {-0.072f,  0.460f,  0.612f},
    { 0.000f, -0.096f,  1.096f}
};

// ---------------------------------------------------------------------------
// 1) fused pool + pad/pack: one block per ic-pair; streams both planes once.
// ---------------------------------------------------------------------------
__global__ void poolpad_kernel(const float* __restrict__ x) {
    const int icp = blockIdx.x;              // 0..383
    const int c0 = 2 * icp;
    __shared__ float s5[2][25];
    __shared__ float s3[2][9];
    const int tid = threadIdx.x;
    if (tid < 25) { s5[0][tid] = 0.f; s5[1][tid] = 0.f; }
    if (tid < 9)  { s3[0][tid] = 0.f; s3[1][tid] = 0.f; }
    __syncthreads();

    const float* p0 = x + (size_t)c0 * HW_;
    const float* p1 = p0 + HW_;
    __half2* dst = d_xp2 + (size_t)icp * XPPL;

    // zero borders of the padded plane
    for (int i = tid; i < XPPL; i += blockDim.x) {
        int r = i >> 7, cix = i & 127;
        bool interior = (r >= 1 && r <= 120 && cix >= 1 && cix <= 120);
        if (!interior) dst[i] = __half2half2(__float2half(0.f));
    }

    // interior: pack to half2 and accumulate pools (1800 tasks of 8 pixels)
    for (int tsk = tid; tsk < 1800; tsk += blockDim.x) {
        int h = tsk / 15;
        int wb = tsk - h * 15;
        int base = h * 120 + wb * 8;
        float a0 = 0.f, a1 = 0.f;
#pragma unroll
        for (int j = 0; j < 8; j++) {
            float v0 = p0[base + j];
            float v1 = p1[base + j];
            a0 += v0; a1 += v1;
            dst[(h + 1) * XPW + (wb * 8 + j + 1)] = __floats2half2_rn(v0, v1);
        }
        int w0 = wb * 8;
        int i5 = (h / 24) * 5 + (w0 / 24);
        int i3 = (h / 40) * 3 + (w0 / 40);
        atomicAdd(&s5[0][i5], a0);
        atomicAdd(&s5[1][i5], a1);
        atomicAdd(&s3[0][i3], a0);
        atomicAdd(&s3[1][i3], a1);
    }
    __syncthreads();

#pragma unroll
    for (int ch = 0; ch < 2; ch++) {
        int c = c0 + ch;
        if (tid < 25) d_att[(size_t)(1536 + c) * 25 + tid] = s5[ch][tid] * (1.f / 576.f);
        if (tid < 9)  d_a3[c * 9 + tid] = s3[ch][tid] * (1.f / 1600.f);
    }
    if (tid == 0) {
#pragma unroll
        for (int ch = 0; ch < 2; ch++) {
            float tot = 0.f;
#pragma unroll
            for (int j = 0; j < 25; j++) tot += s5[ch][j];
            float m = tot * (1.f / 14400.f);
#pragma unroll
            for (int pq = 0; pq < 25; pq++)
                d_att[(size_t)(c0 + ch) * 25 + pq] = m;
        }
    }
}

// ---------------------------------------------------------------------------
// 2) routing net (upsample fused)
// ---------------------------------------------------------------------------
__global__ void route_kernel(const float* __restrict__ w_pw1,
                             const float* __restrict__ w_dw1,
                             const float* __restrict__ w_dw2,
                             const float* __restrict__ w_pw2) {
    __shared__ float h1[SQZ * 25];
    __shared__ float h2[SQZ * 9];
    __shared__ float h3[SQZ];
    const int tid = threadIdx.x;

    for (int tsk = tid; tsk < 768 * 25; tsk += blockDim.x) {
        int c = tsk / 25, pq = tsk - c * 25;
        int p = pq / 5, q = pq - p * 5;
        float s = 0.f;
#pragma unroll
        for (int i = 0; i < 3; i++)
#pragma unroll
            for (int j = 0; j < 3; j++)
                s += c_M35[p][i] * c_M35[q][j] * d_a3[c * 9 + i * 3 + j];
        d_att[(size_t)(768 + c) * 25 + pq] = s;
    }
    __syncthreads();

    for (int tsk = tid; tsk < SQZ * 25; tsk += blockDim.x) {
        int s = tsk / 25, pq = tsk - s * 25;
        const float* wr = w_pw1 + (size_t)s * 2304;
        float acc = 0.f;
        for (int ch = 0; ch < 2304; ch++)
            acc += wr[ch] * d_att[(size_t)ch * 25 + pq];
        h1[tsk] = fmaxf(acc, 0.f);
    }
    __syncthreads();

    for (int tsk = tid; tsk < SQZ * 9; tsk += blockDim.x) {
        int s = tsk / 9;
        int r = tsk - s * 9;
        int p = r / 3, q = r - p * 3;
        float acc = 0.f;
#pragma unroll
        for (int u = 0; u < 3; u++)
#pragma unroll
            for (int v = 0; v < 3; v++)
                acc += h1[s * 25 + (p + u) * 5 + (q + v)] * w_dw1[s * 9 + u * 3 + v];
        h2[tsk] = fmaxf(acc, 0.f);
    }
    __syncthreads();

    if (tid < SQZ) {
        float acc = 0.f;
#pragma unroll
        for (int uv = 0; uv < 9; uv++)
            acc += h2[tid * 9 + uv] * w_dw2[tid * 9 + uv];
        h3[tid] = fmaxf(acc, 0.f);
    }
    __syncthreads();

    for (int o = tid; o < 2304; o += blockDim.x) {
        const float* wr = w_pw2 + (size_t)o * SQZ;
        float acc = 0.f;
#pragma unroll
        for (int s = 0; s < SQZ; s++) acc += wr[s] * h3[s];
        d_route[o] = 1.f / (1.f + expf(-acc));
    }
}

// ---------------------------------------------------------------------------
// 3) weight synthesis -> fp16, tap-major layout
// ---------------------------------------------------------------------------
__global__ void wsyn_kernel(const float* __restrict__ convs) {
    const int oc = blockIdx.x;
    __shared__ float ws[KTOT];
    const int tid = threadIdx.x;

    const float r0 = d_route[oc];
    const float r1 = d_route[768 + oc];
    const float r2 = d_route[1536 + oc];
    const float* c0 = convs + (size_t)oc * KTOT;
    const float* c1 = c0 + (size_t)768 * KTOT;
    const float* c2 = c1 + (size_t)768 * KTOT;

#pragma unroll
    for (int j = 0; j < 27; j++) {
        int i = tid + j * 256;
        ws[i] = r0 * c0[i] + r1 * c1[i] + r2 * c2[i];
    }
    __syncthreads();

    __half* wr = d_w2h + (size_t)oc * KTOT;
#pragma unroll
    for (int j = 0; j < 27; j++) {
        int idx = tid + j * 256;       // idx = tap*768 + ic
        int tap = idx / 768;
        int ic = idx - tap * 768;
        wr[idx] = __float2half(ws[ic * 9 + tap]);
    }
}

// ---------------------------------------------------------------------------
// 4) conv GEMM fp16: BM=128, BN=128, BK=32, 256 thr, 2x4 warps (64x32 tiles)
//    occupancy 2 per SM (smem 48.1KB, <=128 regs)
// ---------------------------------------------------------------------------
__device__ __forceinline__ void mma_fp16(float* c, const uint32_t* a, const uint32_t* b) {
    asm volatile(
        "mma.sync.aligned.m16n8k16.row.col.f32.f16.f16.f32 "
        "{%0,%1,%2,%3}, {%4,%5,%6,%7}, {%8,%9}, {%0,%1,%2,%3};\n"
        : "+f"(c[0]), "+f"(c[1]), "+f"(c[2]), "+f"(c[3])
        : "r"(a[0]), "r"(a[1]), "r"(a[2]), "r"(a[3]),
          "r"(b[0]), "r"(b[1]));
}

__device__ __forceinline__ uint32_t cvta_smem(const void* p) {
    uint32_t a;
    asm("{ .reg .u64 t; cvta.to.shared.u64 t, %1; cvt.u32.u64 %0, t; }"
        : "=r"(a) : "l"(p));
    return a;
}

__device__ __forceinline__ void cp16(uint32_t dst, const void* src) {
    asm volatile("cp.async.cg.shared.global [%0], [%1], 16;\n"
                 :: "r"(dst), "l"(src) : "memory");
}

#define AS2 20                      // half2 per A row (16 used + 4 pad)
#define A_STG_W (128 * AS2)         // 2560 half2 / A stage
#define BS2 136                     // half2 per B k-pair row (128 + 8 pad)
#define B_STG_W (16 * BS2)          // 2176 half2 / B stage
#define SMEM_REQ ((3 * A_STG_W + 2 * B_STG_W) * 4)   // 48128 B

__global__ void __launch_bounds__(256, 2)
conv_gemm_kernel(float* __restrict__ y) {
    extern __shared__ __half2 sm2[];
    __half2* As = sm2;                    // 3 stages
    __half2* Bs = sm2 + 3 * A_STG_W;      // 2 stages
    const uint32_t As_u32 = cvta_smem(As);

    const int tid = threadIdx.x;
    const int lane = tid & 31;
    const int g = lane >> 2, t = lane & 3;
    const int warp = tid >> 5;
    const int wm = warp >> 2, wn = warp & 3;   // 2x4 warps, 64x32 tiles
    const int oc0 = blockIdx.y * 128;
    const int n0 = blockIdx.x * 128;

    // B fill: 128 pixels x 16 k-pairs per stage; each thread does 8 k-pairs
    const int pgrp = tid & 127;           // pixel within tile
    const int khalf = tid >> 7;           // 0 or 1 (k-pair half)
    const int pix = n0 + pgrp;
    const int phh = pix / 120;
    const int pww = pix - phh * 120;

    // A fill: 512 16B-chunks per stage, 2 per thread
    const __half* aSrc = d_w2h + (size_t)oc0 * KTOT;
    const int arow = tid >> 1;
    const int acb0 = (tid & 1) * 2;

    __half2 bR[8];

    auto cpA = [&](int it, int st) {
        uint32_t dbase = As_u32 + (uint32_t)st * (A_STG_W * 4);
        const __half* s0 = aSrc + (size_t)arow * KTOT + it * 32;
#pragma unroll
        for (int j = 0; j < 2; j++) {
            int cb = acb0 + j;
            cp16(dbase + arow * (AS2 * 4) + cb * 16, s0 + cb * 8);
        }
        asm volatile("cp.async.commit_group;\n" ::: "memory");
    };

    auto ldgB = [&](int it) {
        int tap = it / 24;
        int icp0 = (it - tap * 24) * 16 + khalf * 8;
        int du = tap / 3, dv = tap - du * 3;
        const __half2* bp = d_xp2 + (size_t)icp0 * XPPL + (phh + du) * XPW + (pww + dv);
#pragma unroll
        for (int kp = 0; kp < 8; kp++) bR[kp] = bp[(size_t)kp * XPPL];
    };

    auto stsB = [&](int st) {
        __half2* bd = Bs + st * B_STG_W + khalf * (8 * BS2) + pgrp;
#pragma unroll
        for (int kp = 0; kp < 8; kp++) bd[kp * BS2] = bR[kp];
    };

    float acc[4][4][4];
#pragma unroll
    for (int i = 0; i < 4; i++)
#pragma unroll
        for (int j = 0; j < 4; j++)
#pragma unroll
            for (int r = 0; r < 4; r++) acc[i][j][r] = 0.f;

    auto compute = [&](int stA, int stB) {
        const __half2* A = As + stA * A_STG_W;
        const __half2* B = Bs + stB * B_STG_W;
#pragma unroll
        for (int ks = 0; ks < 2; ++ks) {
            const int kb2 = ks * 8;
            uint32_t a[4][4], b[4][2];
#pragma unroll
            for (int i = 0; i < 4; i++) {
                int row = wm * 64 + i * 16 + g;
                a[i][0] = *(const uint32_t*)&A[row * AS2 + kb2 + t];
                a[i][1] = *(const uint32_t*)&A[(row + 8) * AS2 + kb2 + t];
                a[i][2] = *(const uint32_t*)&A[row * AS2 + kb2 + t + 4];
                a[i][3] = *(const uint32_t*)&A[(row + 8) * AS2 + kb2 + t + 4];
            }
#pragma unroll
            for (int j = 0; j < 4; j++) {
                int col = wn * 32 + j * 8 + g;
                b[j][0] = *(const uint32_t*)&B[(kb2 + t) * BS2 + col];
                b[j][1] = *(const uint32_t*)&B[(kb2 + t + 4) * BS2 + col];
            }
#pragma unroll
            for (int i = 0; i < 4; i++)
#pragma unroll
                for (int j = 0; j < 4; j++)
                    mma_fp16(acc[i][j], a[i], b[j]);
        }
    };

    // prologue
    cpA(0, 0);
    cpA(1, 1);
    ldgB(0);
    stsB(0);
    asm volatile("cp.async.wait_group 1;\n" ::: "memory");   // A0 landed
    __syncthreads();

    for (int it = 0; it < NI; ++it) {
        const int stA = it % 3;
        const int stB = it & 1;
        const bool more2 = (it + 2) < NI;
        const bool more1 = (it + 1) < NI;
        if (more2) cpA(it + 2, (it + 2) % 3);
        if (more1) ldgB(it + 1);
        compute(stA, stB);
        if (more1) {
            stsB(stB ^ 1);
            if (more2) { asm volatile("cp.async.wait_group 1;\n" ::: "memory"); }
            else       { asm volatile("cp.async.wait_group 0;\n" ::: "memory"); }
            __syncthreads();
        }
    }

    // epilogue
#pragma unroll
    for (int i = 0; i < 4; i++) {
        int oc = oc0 + wm * 64 + i * 16 + g;
        float* y0 = y + (size_t)oc * HW_;
#pragma unroll
        for (int j = 0; j < 4; j++) {
            int pj = n0 + wn * 32 + j * 8 + 2 * t;
            if (pj < HW_) {
                *reinterpret_cast<float2*>(y0 + pj) =
                    make_float2(acc[i][j][0], acc[i][j][1]);
                *reinterpret_cast<float2*>(y0 + (size_t)8 * HW_ + pj) =
                    make_float2(acc[i][j][2], acc[i][j][3]);
            }
        }
    }
}

// ---------------------------------------------------------------------------
extern "C" void kernel_launch(void* const* d_in, const int* in_sizes, int n_in,
                              void* d_out, int out_size) {
    const float* x     = (const float*)d_in[0];
    const float* convs = (const float*)d_in[1];
    const float* w_pw1 = (const float*)d_in[2];
    const float* w_dw1 = (const float*)d_in[3];
    const float* w_dw2 = (const float*)d_in[4];
    const float* w_pw2 = (const float*)d_in[5];
    float* y = (float*)d_out;

    poolpad_kernel<<<384, 256>>>(x);
    route_kernel<<<1, 1024>>>(w_pw1, w_dw1, w_dw2, w_pw2);
    wsyn_kernel<<<768, 256>>>(convs);

    cudaFuncSetAttribute(conv_gemm_kernel,
                         cudaFuncAttributeMaxDynamicSharedMemorySize, SMEM_REQ);
    conv_gemm_kernel<<<dim3(113, 6), 256, SMEM_REQ>>>(y);   // 4th launch -> ncu
}

// round 6
// speedup vs baseline: 2.9401x; 1.4462x over previous
#include <cuda_runtime.h>
#include <cuda_fp16.h>
#include <cstdint>

// ---------------------------------------------------------------------------
// DyResConv inference, batch=1 — fp16 mma.sync m16n8k16 implicit GEMM
//   GEMM: C[768 x 14400] = W2[768 x 6912] * im2col(x),  k = tap*768 + ic
// R6: fragment-layout A (LDS.128), cp.async B fill, 3-stage pipe,
//     route rebuilt (coalesced, multi-block + spin grid-sync)
// ---------------------------------------------------------------------------

#define CCH 768
#define SQZ 48
#define HW_ 14400
#define KTOT 6912
#define NI   216          // 6912 / 32  K-iterations
#define XPW  128
#define XPR  124
#define XPPL (XPW * XPR)  // 15872

// scratch (device globals; no allocation allowed)
__device__ float d_attT[25 * 2304];             // transposed attention maps
__device__ float d_route[2304];
__device__ float d_h1g[SQZ * 25];
__device__ int   d_sync;
__device__ __half  d_w2f[CCH * KTOT];           // weights in mma-fragment order
__device__ __half2 d_xp2[(CCH / 2) * XPPL];     // padded x, ic-pairs packed

__constant__ float c_M35[5][3] = {
    { 1.096f, -0.096f,  0.000f},
    { 0.612f,  0.460f, -0.072f},
    { 0.000f,  1.000f,  0.000f},
    {-0.072f,  0.460f,  0.612f},
    { 0.000f, -0.096f,  1.096f}
};

// ---------------------------------------------------------------------------
// 1) fused pool + pad/pack + upsample; writes attT directly.
// ---------------------------------------------------------------------------
__global__ void poolpad_kernel(const float* __restrict__ x) {
    const int icp = blockIdx.x;              // 0..383
    const int c0 = 2 * icp;
    __shared__ float s5[2][25];
    __shared__ float s3[2][9];
    const int tid = threadIdx.x;
    if (tid < 25) { s5[0][tid] = 0.f; s5[1][tid] = 0.f; }
    if (tid < 9)  { s3[0][tid] = 0.f; s3[1][tid] = 0.f; }
    __syncthreads();

    const float* p0 = x + (size_t)c0 * HW_;
    const float* p1 = p0 + HW_;
    __half2* dst = d_xp2 + (size_t)icp * XPPL;

    for (int i = tid; i < XPPL; i += blockDim.x) {
        int r = i >> 7, cix = i & 127;
        bool interior = (r >= 1 && r <= 120 && cix >= 1 && cix <= 120);
        if (!interior) dst[i] = __half2half2(__float2half(0.f));
    }

    for (int tsk = tid; tsk < 1800; tsk += blockDim.x) {
        int h = tsk / 15;
        int wb = tsk - h * 15;
        int base = h * 120 + wb * 8;
        float a0 = 0.f, a1 = 0.f;
#pragma unroll
        for (int j = 0; j < 8; j++) {
            float v0 = p0[base + j];
            float v1 = p1[base + j];
            a0 += v0; a1 += v1;
            dst[(h + 1) * XPW + (wb * 8 + j + 1)] = __floats2half2_rn(v0, v1);
        }
        int w0 = wb * 8;
        int i5 = (h / 24) * 5 + (w0 / 24);
        int i3 = (h / 40) * 3 + (w0 / 40);
        atomicAdd(&s5[0][i5], a0);
        atomicAdd(&s5[1][i5], a1);
        atomicAdd(&s3[0][i3], a0);
        atomicAdd(&s3[1][i3], a1);
    }
    __syncthreads();

    if (tid < 50) {
        int ch_l = tid / 25;
        int pq = tid - ch_l * 25;
        int c = c0 + ch_l;
        float tot = 0.f;
#pragma unroll
        for (int j = 0; j < 25; j++) tot += s5[ch_l][j];
        d_attT[pq * 2304 + c] = tot * (1.f / 14400.f);              // a1
        d_attT[pq * 2304 + 1536 + c] = s5[ch_l][pq] * (1.f / 576.f); // a5
        int p = pq / 5, q = pq - p * 5;
        float s = 0.f;
#pragma unroll
        for (int i = 0; i < 3; i++)
#pragma unroll
            for (int j = 0; j < 3; j++)
                s += c_M35[p][i] * c_M35[q][j] * s3[ch_l][i * 3 + j];
        d_attT[pq * 2304 + 768 + c] = s * (1.f / 1600.f);            // a3u
    }
}

// ---------------------------------------------------------------------------
// 2) routing net: grid 48 (stage1, coalesced) + spin grid-sync, block 0 tail
// ---------------------------------------------------------------------------
__global__ void route_kernel(const float* __restrict__ w_pw1,
                             const float* __restrict__ w_dw1,
                             const float* __restrict__ w_dw2,
                             const float* __restrict__ w_pw2) {
    const int s = blockIdx.x;
    const int tid = threadIdx.x;

    // stage 1: h1[s][pq] = relu( dot(w_pw1[s,:], attT[:,pq over ch]) )
    {
        float acc[25];
#pragma unroll
        for (int pq = 0; pq < 25; pq++) acc[pq] = 0.f;
        for (int ch = tid; ch < 2304; ch += 256) {
            float wv = w_pw1[(size_t)s * 2304 + ch];
#pragma unroll
            for (int pq = 0; pq < 25; pq++)
                acc[pq] += wv * d_attT[pq * 2304 + ch];
        }
        __shared__ float red[25][257];
#pragma unroll
        for (int pq = 0; pq < 25; pq++) red[pq][tid] = acc[pq];
        __syncthreads();
        if (tid < 25) {
            float sum = 0.f;
            for (int i = 0; i < 256; i++) sum += red[tid][i];
            d_h1g[s * 25 + tid] = fmaxf(sum, 0.f);
        }
    }
    __threadfence();
    __syncthreads();

    if (s != 0) {
        if (tid == 0) atomicAdd(&d_sync, 1);
        return;
    }
    if (tid == 0) {
        atomicAdd(&d_sync, 1);
        while (atomicAdd(&d_sync, 0) < 48) { }
    }
    __syncthreads();
    __threadfence();

    // block 0: dw1 -> dw2 -> pw2 -> sigmoid
    __shared__ float h1[SQZ * 25];
    __shared__ float h2[SQZ * 9];
    __shared__ float h3[SQZ];
    for (int i = tid; i < SQZ * 25; i += 256) h1[i] = d_h1g[i];
    __syncthreads();

    for (int tsk = tid; tsk < SQZ * 9; tsk += 256) {
        int ss = tsk / 9;
        int r = tsk - ss * 9;
        int p = r / 3, q = r - p * 3;
        float acc = 0.f;
#pragma unroll
        for (int u = 0; u < 3; u++)
#pragma unroll
            for (int v = 0; v < 3; v++)
                acc += h1[ss * 25 + (p + u) * 5 + (q + v)] * w_dw1[ss * 9 + u * 3 + v];
        h2[tsk] = fmaxf(acc, 0.f);
    }
    __syncthreads();

    if (tid < SQZ) {
        float acc = 0.f;
#pragma unroll
        for (int uv = 0; uv < 9; uv++)
            acc += h2[tid * 9 + uv] * w_dw2[tid * 9 + uv];
        h3[tid] = fmaxf(acc, 0.f);
    }
    __syncthreads();

    for (int o = tid; o < 2304; o += 256) {
        const float* wr = w_pw2 + (size_t)o * SQZ;
        float acc = 0.f;
#pragma unroll
        for (int ss = 0; ss < SQZ; ss++) acc += wr[ss] * h3[ss];
        d_route[o] = 1.f / (1.f + expf(-acc));
    }
    __syncthreads();
    if (tid == 0) d_sync = 0;   // reset for next graph replay
}

// ---------------------------------------------------------------------------
// 3) weight synthesis -> fp16 directly in mma-fragment layout.
//    chunk(ocb, kb, lane)[8 halves]: rows ocb*16+{g,g+8}, cols kb*16+{2t,2t+1,2t+8,2t+9}
//    half index h = chalf*4 + rowhalf*2 + odd;  lane = g*4 + t
// ---------------------------------------------------------------------------
__global__ void wsyn_kernel(const float* __restrict__ convs) {
    const int oc = blockIdx.x;
    __shared__ float ws[KTOT];
    const int tid = threadIdx.x;

    const float r0 = d_route[oc];
    const float r1 = d_route[768 + oc];
    const float r2 = d_route[1536 + oc];
    const float* c0 = convs + (size_t)oc * KTOT;
    const float* c1 = c0 + (size_t)768 * KTOT;
    const float* c2 = c1 + (size_t)768 * KTOT;

#pragma unroll
    for (int j = 0; j < 27; j++) {
        int i = tid + j * 256;
        ws[i] = r0 * c0[i] + r1 * c1[i] + r2 * c2[i];
    }
    __syncthreads();

    const int g = oc & 7;
    const int rh = (oc >> 3) & 1;
    const int ocb = oc >> 4;
#pragma unroll
    for (int j = 0; j < 27; j++) {
        int idx = tid + j * 256;        // k = tap*768 + ic
        int tap = idx / 768;
        int ic = idx - tap * 768;
        int kb = idx >> 4;
        int kc = idx & 15;
        int t = (kc >> 1) & 3;
        int chalf = kc >> 3;
        int odd = kc & 1;
        int lane = (g << 2) | t;
        int h = chalf * 4 + rh * 2 + odd;
        d_w2f[((((size_t)ocb * 432 + kb) * 32 + lane) << 3) + h] =
            __float2half(ws[ic * 9 + tap]);
    }
}

// ---------------------------------------------------------------------------
// 4) conv GEMM fp16: BM=128, BN=128, BK=32, 256 thr, 2x4 warps, occ 2,
//    3-stage cp.async pipeline for A (fragment 16B chunks) and B (4B gather)
// ---------------------------------------------------------------------------
__device__ __forceinline__ void mma_fp16(float* c, const uint32_t* a, const uint32_t* b) {
    asm volatile(
        "mma.sync.aligned.m16n8k16.row.col.f32.f16.f16.f32 "
        "{%0,%1,%2,%3}, {%4,%5,%6,%7}, {%8,%9}, {%0,%1,%2,%3};\n"
        : "+f"(c[0]), "+f"(c[1]), "+f"(c[2]), "+f"(c[3])
        : "r"(a[0]), "r"(a[1]), "r"(a[2]), "r"(a[3]),
          "r"(b[0]), "r"(b[1]));
}

__device__ __forceinline__ uint32_t cvta_smem(const void* p) {
    uint32_t a;
    asm("{ .reg .u64 t; cvta.to.shared.u64 t, %1; cvt.u32.u64 %0, t; }"
        : "=r"(a) : "l"(p));
    return a;
}

__device__ __forceinline__ void cp16(uint32_t dst, const void* src) {
    asm volatile("cp.async.cg.shared.global [%0], [%1], 16;\n"
                 :: "r"(dst), "l"(src) : "memory");
}
__device__ __forceinline__ void cp4(uint32_t dst, const void* src) {
    asm volatile("cp.async.ca.shared.global [%0], [%1], 4;\n"
                 :: "r"(dst), "l"(src) : "memory");
}

#define ASTG 8192                   // A stage bytes (512 chunks * 16B)
#define BS2  136                    // half2 per B k-pair row (128 + 8 pad)
#define BSTG (16 * BS2 * 4)         // 8704 B
#define SMEM_REQ (3 * ASTG + 3 * BSTG)   // 50688 B

__global__ void __launch_bounds__(256, 2)
conv_gemm_kernel(float* __restrict__ y) {
    extern __shared__ char smraw[];
    char* Abase = smraw;
    char* Bbase = smraw + 3 * ASTG;
    const uint32_t As_u32 = cvta_smem(Abase);
    const uint32_t Bs_u32 = cvta_smem(Bbase);

    const int tid = threadIdx.x;
    const int lane = tid & 31;
    const int g = lane >> 2, t = lane & 3;
    const int warp = tid >> 5;
    const int wm = warp >> 2, wn = warp & 3;   // 2x4 warps, 64x32 tiles
    const int oc0 = blockIdx.y * 128;
    const int ocb0 = blockIdx.y * 8;
    const int n0 = blockIdx.x * 128;

    const int pgrp = tid & 127;
    const int khalf = tid >> 7;
    const int pix = n0 + pgrp;
    const int phh = pix / 120;
    const int pww = pix - phh * 120;

    auto cpA = [&](int it, int st) {
        uint32_t ab = As_u32 + st * ASTG;
#pragma unroll
        for (int j = 0; j < 2; j++) {
            int c = tid + j * 256;
            const __half* src = d_w2f +
                ((((size_t)(ocb0 + (c >> 6)) * 432) + (it * 2 + ((c >> 5) & 1))) * 32 + (c & 31)) * 8;
            cp16(ab + c * 16, src);
        }
    };

    auto cpB = [&](int it, int st) {
        int tap = it / 24;
        int icp0 = (it - tap * 24) * 16 + khalf * 8;
        int du = tap / 3, dv = tap - du * 3;
        const __half2* bp = d_xp2 + (size_t)icp0 * XPPL + (phh + du) * XPW + (pww + dv);
        uint32_t bd = Bs_u32 + st * BSTG + ((khalf * 8) * BS2 + pgrp) * 4;
#pragma unroll
        for (int q = 0; q < 8; q++)
            cp4(bd + q * (BS2 * 4), bp + (size_t)q * XPPL);
    };

    float acc[4][4][4];
#pragma unroll
    for (int i = 0; i < 4; i++)
#pragma unroll
        for (int j = 0; j < 4; j++)
#pragma unroll
            for (int r = 0; r < 4; r++) acc[i][j][r] = 0.f;

    auto compute = [&](int st) {
        const char* Ab = Abase + st * ASTG;
        const __half2* B = (const __half2*)(Bbase + st * BSTG);
#pragma unroll
        for (int ks = 0; ks < 2; ++ks) {
            uint4 a[4];
            uint32_t b[4][2];
#pragma unroll
            for (int i = 0; i < 4; i++)
                a[i] = *(const uint4*)(Ab + ((((wm * 4 + i) * 2 + ks) * 32 + lane) << 4));
            const int kb2 = ks * 8;
#pragma unroll
            for (int j = 0; j < 4; j++) {
                int col = wn * 32 + j * 8 + g;
                b[j][0] = *(const uint32_t*)&B[(kb2 + t) * BS2 + col];
                b[j][1] = *(const uint32_t*)&B[(kb2 + t + 4) * BS2 + col];
            }
#pragma unroll
            for (int i = 0; i < 4; i++)
#pragma unroll
                for (int j = 0; j < 4; j++)
                    mma_fp16(acc[i][j], (const uint32_t*)&a[i], b[j]);
        }
    };

    // prologue: stages 0 and 1 in flight
    cpA(0, 0); cpB(0, 0);
    asm volatile("cp.async.commit_group;\n" ::: "memory");
    cpA(1, 1); cpB(1, 1);
    asm volatile("cp.async.commit_group;\n" ::: "memory");
    asm volatile("cp.async.wait_group 1;\n" ::: "memory");
    __syncthreads();

    for (int it = 0; it < NI; ++it) {
        const int st = it % 3;
        const bool more2 = (it + 2) < NI;
        if (more2) {
            int st2 = (it + 2) % 3;
            cpA(it + 2, st2); cpB(it + 2, st2);
            asm volatile("cp.async.commit_group;\n" ::: "memory");
        }
        compute(st);
        if (more2) { asm volatile("cp.async.wait_group 1;\n" ::: "memory"); }
        else       { asm volatile("cp.async.wait_group 0;\n" ::: "memory"); }
        __syncthreads();
    }

    // epilogue
#pragma unroll
    for (int i = 0; i < 4; i++) {
        int oc = oc0 + wm * 64 + i * 16 + g;
        float* y0 = y + (size_t)oc * HW_;
#pragma unroll
        for (int j = 0; j < 4; j++) {
            int pj = n0 + wn * 32 + j * 8 + 2 * t;
            if (pj < HW_) {
                *reinterpret_cast<float2*>(y0 + pj) =
                    make_float2(acc[i][j][0], acc[i][j][1]);
                *reinterpret_cast<float2*>(y0 + (size_t)8 * HW_ + pj) =
                    make_float2(acc[i][j][2], acc[i][j][3]);
            }
        }
    }
}

// ---------------------------------------------------------------------------
extern "C" void kernel_launch(void* const* d_in, const int* in_sizes, int n_in,
                              void* d_out, int out_size) {
    const float* x     = (const float*)d_in[0];
    const float* convs = (const float*)d_in[1];
    const float* w_pw1 = (const float*)d_in[2];
    const float* w_dw1 = (const float*)d_in[3];
    const float* w_dw2 = (const float*)d_in[4];
    const float* w_pw2 = (const float*)d_in[5];
    float* y = (float*)d_out;

    poolpad_kernel<<<384, 256>>>(x);
    route_kernel<<<48, 256>>>(w_pw1, w_dw1, w_dw2, w_pw2);
    wsyn_kernel<<<768, 256>>>(convs);

    cudaFuncSetAttribute(conv_gemm_kernel,
                         cudaFuncAttributeMaxDynamicSharedMemorySize, SMEM_REQ);
    conv_gemm_kernel<<<dim3(113, 6), 256, SMEM_REQ>>>(y);   // 4th launch -> ncu
}